// round 7
// baseline (speedup 1.0000x reference)
#include <cuda_runtime.h>
#include <math_constants.h>

#define B_ROWS   131072
#define D_EMB    256
#define QSIZE    128
#define TM       128
#define TILES_M  (B_ROWS / TM)   // 1024
#define MARGIN   1.0f

// ---------------- device scratch (static) ----------------
__device__ int    g_counts[4];
__device__ int    g_buckets[4 * B_ROWS];
__device__ float  g_rowloss[B_ROWS];
__device__ double g_bsum[256];

// ---------------- small kernels ----------------
__global__ void reset_kernel() {
    if (threadIdx.x < 4) g_counts[threadIdx.x] = 0;
}
__global__ void classify_kernel(const int* __restrict__ node_type) {
    __shared__ int s_cnt[4];
    __shared__ int s_base[4];
    int tid = threadIdx.x;
    int i = blockIdx.x * blockDim.x + tid;
    if (tid < 4) s_cnt[tid] = 0;
    __syncthreads();
    int t = node_type[i];
    int g = (t == 5) ? 0 : (t == 6) ? 1 : (t == 7) ? 2 : 3;
    int p = atomicAdd(&s_cnt[g], 1);
    __syncthreads();
    if (tid < 4) s_base[tid] = atomicAdd(&g_counts[tid], s_cnt[tid]);
    __syncthreads();
    g_buckets[g * B_ROWS + s_base[g] + p] = i;
}

// ---------------- smem layout ----------------
#define ROWB     68
#define T_FLOATS (128 * ROWB)
#define OFF_A    0
#define OFF_B    (T_FLOATS * 4)
#define OFF_ROWS (2 * T_FLOATS * 4)
#define OFF_ZNP  (OFF_ROWS + 512)
#define OFF_ENP  (OFF_ZNP + 1024)
#define OFF_ZN   (OFF_ENP + 1024)
#define OFF_EN   (OFF_ZN + 512)
#define OFF_SEL  (OFF_EN + 512)
#define OFF_NC   (OFF_SEL + 512)
#define OFF_CAND (OFF_NC + 512)
#define OFF_LOSS (OFF_CAND + 4096)
#define OFF_PMIN (OFF_LOSS + 1024)   // 256 float (row x wn)
#define OFF_PCOL (OFF_PMIN + 1024)   // 256 int
#define OFF_RMIN (OFF_PCOL + 1024)   // 128 float
#define SMEM_DYN (OFF_RMIN + 512)

__device__ __forceinline__ float tf32_rna(float x) {
    unsigned r; asm("cvt.rna.tf32.f32 %0, %1;" : "=r"(r) : "f"(x));
    return __uint_as_float(r);
}
__device__ __forceinline__ float4 tf32_rna4(float4 v) {
    return make_float4(tf32_rna(v.x), tf32_rna(v.y), tf32_rna(v.z), tf32_rna(v.w));
}
__device__ __forceinline__ void mma_tf32(float* d, const unsigned* a,
                                         const unsigned* b) {
    asm volatile(
        "mma.sync.aligned.m16n8k8.row.col.f32.tf32.tf32.f32 "
        "{%0,%1,%2,%3}, {%4,%5,%6,%7}, {%8,%9}, {%0,%1,%2,%3};"
        : "+f"(d[0]), "+f"(d[1]), "+f"(d[2]), "+f"(d[3])
        : "r"(a[0]), "r"(a[1]), "r"(a[2]), "r"(a[3]), "r"(b[0]), "r"(b[1]));
}

// ---------------- main kernel ----------------
__global__ void __launch_bounds__(256, 2) vq_mma_kernel(
    const float* __restrict__ z, const float* __restrict__ cb,
    float* __restrict__ out)
{
    extern __shared__ char sm[];
    const int g   = blockIdx.y;
    const int tid = threadIdx.x;
    const int cnt   = g_counts[g];
    const int start = blockIdx.x * TM;
    if (start >= cnt) return;

    float* smA    = (float*)(sm + OFF_A);
    float* smB    = (float*)(sm + OFF_B);
    int*   s_rows = (int*)  (sm + OFF_ROWS);
    float* s_znp  = (float*)(sm + OFF_ZNP);
    float* s_enp  = (float*)(sm + OFF_ENP);
    float* s_zn   = (float*)(sm + OFF_ZN);
    float* s_en   = (float*)(sm + OFF_EN);
    int*   s_sel  = (int*)  (sm + OFF_SEL);
    int*   s_nc   = (int*)  (sm + OFF_NC);
    int*   s_cand = (int*)  (sm + OFF_CAND);
    float* s_loss = (float*)(sm + OFF_LOSS);
    float* s_pmin = (float*)(sm + OFF_PMIN);
    int*   s_pcol = (int*)  (sm + OFF_PCOL);
    float* s_rmin = (float*)(sm + OFF_RMIN);

    if (tid < TM) {
        int r = (start + tid < cnt) ? g_buckets[g * B_ROWS + start + tid] : -1;
        s_rows[tid] = r;
        s_nc[tid] = 0;
    }
    __syncthreads();

    const int lrow = tid >> 1, lh = tid & 1;
    const int gr = s_rows[lrow];
    const float* zrow = z  + (size_t)(gr < 0 ? 0 : gr) * D_EMB;
    const float* erow = cb + (size_t)(g * QSIZE + lrow) * D_EMB;

    // 2-D warp tiling: 4 warp-rows x 2 warp-cols; warp tile = 32 rows x 64 cols
    const int w = tid >> 5, lane = tid & 31;
    const int gq = lane >> 2, t = lane & 3;
    const int wm = w >> 1, wn = w & 1;
    const int RW = wm * 32;          // warp row base
    const int CW = wn * 64;          // warp col base

    float acc[2][8][4];
    #pragma unroll
    for (int i = 0; i < 2; ++i)
        #pragma unroll
        for (int nf = 0; nf < 8; ++nf)
            #pragma unroll
            for (int q = 0; q < 4; ++q) acc[i][nf][q] = 0.f;

    float zn_acc = 0.f, en_acc = 0.f;

    #pragma unroll 1
    for (int c = 0; c < 4; ++c) {
        const int kbase = c * 64 + lh * 32;
        const unsigned aoff = lrow * ROWB + lh * 32;

        float4 vz = *(const float4*)(zrow + kbase);
        float4 ve = *(const float4*)(erow + kbase);

        __syncthreads();   // previous chunk's mma reads done

        #pragma unroll
        for (int j = 0; j < 8; ++j) {
            float4 nz = vz, ne = ve;
            if (j < 7) {
                nz = *(const float4*)(zrow + kbase + 4 * j + 4);
                ne = *(const float4*)(erow + kbase + 4 * j + 4);
            }
            zn_acc += vz.x * vz.x; zn_acc += vz.y * vz.y;
            zn_acc += vz.z * vz.z; zn_acc += vz.w * vz.w;
            en_acc += ve.x * ve.x; en_acc += ve.y * ve.y;
            en_acc += ve.z * ve.z; en_acc += ve.w * ve.w;
            *(float4*)(smA + aoff + 4 * j) = tf32_rna4(vz);
            *(float4*)(smB + aoff + 4 * j) = tf32_rna4(ve);
            vz = nz; ve = ne;
        }
        __syncthreads();

        #pragma unroll
        for (int ks = 0; ks < 8; ++ks) {
            unsigned a[2][4];
            #pragma unroll
            for (int i = 0; i < 2; ++i) {
                const unsigned abase =
                    (unsigned)(RW + i * 16 + gq) * ROWB + ks * 8 + t;
                a[i][0] = *(const unsigned*)(smA + abase);
                a[i][1] = *(const unsigned*)(smA + abase + 8 * ROWB);
                a[i][2] = *(const unsigned*)(smA + abase + 4);
                a[i][3] = *(const unsigned*)(smA + abase + 8 * ROWB + 4);
            }
            unsigned b[8][2];
            #pragma unroll
            for (int nf = 0; nf < 8; ++nf) {
                const unsigned bbase =
                    (unsigned)(CW + nf * 8 + gq) * ROWB + ks * 8 + t;
                b[nf][0] = *(const unsigned*)(smB + bbase);
                b[nf][1] = *(const unsigned*)(smB + bbase + 4);
            }
            #pragma unroll
            for (int i = 0; i < 2; ++i)
                #pragma unroll
                for (int nf = 0; nf < 8; ++nf)
                    mma_tf32(acc[i][nf], a[i], b[nf]);
        }
    }

    s_znp[tid] = zn_acc;
    s_enp[tid] = en_acc;
    __syncthreads();
    if (tid < TM) {
        s_zn[tid] = s_znp[2 * tid] + s_znp[2 * tid + 1];
        s_en[tid] = s_enp[2 * tid] + s_enp[2 * tid + 1];
    }
    __syncthreads();

    // ---- per-warp partial argmin over its 64 cols, 4 rows/thread ----
    #pragma unroll
    for (int i = 0; i < 2; ++i) {
        #pragma unroll
        for (int h = 0; h < 2; ++h) {           // q-pair half: rows gq / gq+8
            const int row = RW + i * 16 + gq + h * 8;
            const float zn = s_zn[row];
            float v = CUDART_INF_F;  int cbest = 0x7fffffff;
            #pragma unroll
            for (int nf = 0; nf < 8; ++nf) {
                #pragma unroll
                for (int q = 0; q < 2; ++q) {
                    int col = CW + nf * 8 + 2 * t + q;
                    float s = fmaf(-2.f, acc[i][nf][h * 2 + q], zn + s_en[col]);
                    if (s < v || (s == v && col < cbest)) { v = s; cbest = col; }
                }
            }
            #pragma unroll
            for (int off = 1; off < 4; off <<= 1) {
                float v2 = __shfl_xor_sync(0xffffffffu, v, off);
                int   c2 = __shfl_xor_sync(0xffffffffu, cbest, off);
                if (v2 < v || (v2 == v && c2 < cbest)) { v = v2; cbest = c2; }
            }
            if (t == 0) {
                s_pmin[row * 2 + wn] = v;
                s_pcol[row * 2 + wn] = cbest;
            }
        }
    }
    __syncthreads();

    // combine the two warp-halves per row
    if (tid < TM) {
        float v0 = s_pmin[tid * 2], v1 = s_pmin[tid * 2 + 1];
        int   c0 = s_pcol[tid * 2], c1 = s_pcol[tid * 2 + 1];
        bool take1 = (v1 < v0) || (v1 == v0 && c1 < c0);
        s_rmin[tid] = take1 ? v1 : v0;
        s_sel[tid]  = take1 ? c1 : c0;
    }
    __syncthreads();

    // ---- candidate collection within MARGIN of row min ----
    #pragma unroll
    for (int i = 0; i < 2; ++i) {
        #pragma unroll
        for (int h = 0; h < 2; ++h) {
            const int row = RW + i * 16 + gq + h * 8;
            const float zn  = s_zn[row];
            const float thr = s_rmin[row] + MARGIN;
            #pragma unroll
            for (int nf = 0; nf < 8; ++nf) {
                #pragma unroll
                for (int q = 0; q < 2; ++q) {
                    int col = CW + nf * 8 + 2 * t + q;
                    float s = fmaf(-2.f, acc[i][nf][h * 2 + q], zn + s_en[col]);
                    if (s <= thr) {
                        int p = atomicAdd(&s_nc[row], 1);
                        if (p < 8) s_cand[row * 8 + p] = col;
                    }
                }
            }
        }
    }
    __syncthreads();

    // ---- exact fp32 rescue for ambiguous rows (warp per 16-row slice) ----
    for (int m = w * 16; m < w * 16 + 16; ++m) {
        int nc = s_nc[m];
        int r  = s_rows[m];
        if (r < 0 || nc <= 1) continue;
        const float* zr = z + (size_t)r * D_EMB;
        float zn = s_zn[m];
        float bestv = CUDART_INF_F;  int bestc = 0x7fffffff;
        int nit = (nc <= 8) ? nc : QSIZE;
        for (int i = 0; i < nit; ++i) {
            int col = (nc <= 8) ? s_cand[m * 8 + i] : i;
            const float* er = cb + (size_t)(g * QSIZE + col) * D_EMB;
            float p = 0.f;
            #pragma unroll
            for (int j = 0; j < 8; ++j)
                p = fmaf(zr[lane + 32 * j], er[lane + 32 * j], p);
            #pragma unroll
            for (int off = 16; off; off >>= 1)
                p += __shfl_xor_sync(0xffffffffu, p, off);
            float sc = fmaf(-2.f, p, zn + s_en[col]);
            if (sc < bestv || (sc == bestv && col < bestc)) { bestv = sc; bestc = col; }
        }
        if (lane == 0) s_sel[m] = bestc;
    }
    __syncthreads();

    if (tid < TM) {
        int r = s_rows[tid];
        if (r >= 0) out[2 + r] = (float)(g * QSIZE + s_sel[tid]);
    }

    // ---- epilogue: st = z + (q - z), per-row loss ----
    {
        int m = tid >> 1, h = tid & 1;
        int r = s_rows[m];
        float lsum = 0.f;
        if (r >= 0) {
            int code = g * QSIZE + s_sel[m];
            const float* zr = z  + (size_t)r    * D_EMB + h * 128;
            const float* qr = cb + (size_t)code * D_EMB + h * 128;
            float* so = out + 2 + B_ROWS + (size_t)r * D_EMB + h * 128;
            #pragma unroll 4
            for (int cc = 0; cc < 128; cc += 4) {
                float4 zv = *(const float4*)(zr + cc);
                float4 qv = *(const float4*)(qr + cc);
                float dx = qv.x - zv.x, dy = qv.y - zv.y;
                float dz = qv.z - zv.z, dw = qv.w - zv.w;
                *(float2*)(so + cc)     = make_float2(zv.x + dx, zv.y + dy);
                *(float2*)(so + cc + 2) = make_float2(zv.z + dz, zv.w + dw);
                lsum += dx * dx; lsum += dy * dy; lsum += dz * dz; lsum += dw * dw;
            }
        }
        s_loss[tid] = lsum;
    }
    __syncthreads();
    if (tid < TM) {
        int r = s_rows[tid];
        if (r >= 0) g_rowloss[r] = s_loss[2 * tid] + s_loss[2 * tid + 1];
    }
}

// ---------------- loss reduction ----------------
__global__ void rowloss_reduce_kernel() {
    __shared__ double sd[256];
    int base = blockIdx.x * 512;
    double s = (double)g_rowloss[base + threadIdx.x]
             + (double)g_rowloss[base + 256 + threadIdx.x];
    sd[threadIdx.x] = s;
    __syncthreads();
    #pragma unroll
    for (int o = 128; o; o >>= 1) {
        if (threadIdx.x < o) sd[threadIdx.x] += sd[threadIdx.x + o];
        __syncthreads();
    }
    if (threadIdx.x == 0) g_bsum[blockIdx.x] = sd[0];
}

__global__ void finalize_kernel(float* __restrict__ out) {
    __shared__ double sd[256];
    sd[threadIdx.x] = g_bsum[threadIdx.x];
    __syncthreads();
    #pragma unroll
    for (int o = 128; o; o >>= 1) {
        if (threadIdx.x < o) sd[threadIdx.x] += sd[threadIdx.x + o];
        __syncthreads();
    }
    if (threadIdx.x == 0) {
        float vq = (float)(sd[0] / ((double)B_ROWS * (double)D_EMB));
        out[0] = vq;
        out[1] = 0.25f * vq;
    }
}

// ---------------- launch ----------------
extern "C" void kernel_launch(void* const* d_in, const int* in_sizes, int n_in,
                              void* d_out, int out_size) {
    const int*   node_type = (const int*)d_in[0];
    const float* z         = (const float*)d_in[1];
    const float* cb        = (const float*)d_in[2];
    float* out = (float*)d_out;

    cudaFuncSetAttribute(vq_mma_kernel,
                         cudaFuncAttributeMaxDynamicSharedMemorySize, SMEM_DYN);

    reset_kernel<<<1, 32>>>();
    classify_kernel<<<B_ROWS / 256, 256>>>(node_type);
    dim3 grid(TILES_M, 4);
    vq_mma_kernel<<<grid, 256, SMEM_DYN>>>(z, cb, out);
    rowloss_reduce_kernel<<<256, 256>>>();
    finalize_kernel<<<1, 256>>>(out);
}

// round 8
// speedup vs baseline: 1.0363x; 1.0363x over previous
#include <cuda_runtime.h>
#include <math_constants.h>

#define B_ROWS   131072
#define D_EMB    256
#define QSIZE    128
#define TM       128
#define TILES_M  (B_ROWS / TM)   // 1024
#define MARGIN   2.5f

// ---------------- device scratch (static) ----------------
__device__ int    g_counts[4];
__device__ int    g_buckets[4 * B_ROWS];
__device__ float  g_enorm[512];
__device__ float  g_rowloss[B_ROWS];
__device__ double g_bsum[256];

// ---------------- small kernels ----------------
__global__ void reset_kernel() {
    if (threadIdx.x < 4) g_counts[threadIdx.x] = 0;
}
__global__ void classify_kernel(const int* __restrict__ node_type) {
    __shared__ int s_cnt[4];
    __shared__ int s_base[4];
    int tid = threadIdx.x;
    int i = blockIdx.x * blockDim.x + tid;
    if (tid < 4) s_cnt[tid] = 0;
    __syncthreads();
    int t = node_type[i];
    int g = (t == 5) ? 0 : (t == 6) ? 1 : (t == 7) ? 2 : 3;
    int p = atomicAdd(&s_cnt[g], 1);
    __syncthreads();
    if (tid < 4) s_base[tid] = atomicAdd(&g_counts[tid], s_cnt[tid]);
    __syncthreads();
    g_buckets[g * B_ROWS + s_base[g] + p] = i;
}
// exact fp32 code norms (one warp per code)
__global__ void enorm_kernel(const float* __restrict__ cb) {
    int code = blockIdx.x * 8 + (threadIdx.x >> 5);
    int lane = threadIdx.x & 31;
    const float* row = cb + (size_t)code * D_EMB;
    float s = 0.f;
    #pragma unroll
    for (int j = 0; j < 8; ++j)
        s = fmaf(row[lane + 32 * j], row[lane + 32 * j], s);
    #pragma unroll
    for (int o = 16; o; o >>= 1) s += __shfl_xor_sync(0xffffffffu, s, o);
    if (lane == 0) g_enorm[code] = s;
}

// ---------------- cp.async helpers ----------------
__device__ __forceinline__ unsigned smem_u32(const void* p) {
    unsigned a;
    asm("{ .reg .u64 t; cvta.to.shared.u64 t, %1; cvt.u32.u64 %0, t; }"
        : "=r"(a) : "l"(p));
    return a;
}
__device__ __forceinline__ void cp16(unsigned saddr, const void* gaddr) {
    asm volatile("cp.async.cg.shared.global [%0], [%1], 16;"
                 :: "r"(saddr), "l"(gaddr) : "memory");
}
#define CP_COMMIT() asm volatile("cp.async.commit_group;" ::: "memory")
#define CP_WAIT1()  asm volatile("cp.async.wait_group 1;" ::: "memory")
#define CP_WAIT0()  asm volatile("cp.async.wait_group 0;" ::: "memory")

__device__ __forceinline__ void mma_tf32(float* d, const unsigned* a,
                                         const unsigned* b) {
    asm volatile(
        "mma.sync.aligned.m16n8k8.row.col.f32.tf32.tf32.f32 "
        "{%0,%1,%2,%3}, {%4,%5,%6,%7}, {%8,%9}, {%0,%1,%2,%3};"
        : "+f"(d[0]), "+f"(d[1]), "+f"(d[2]), "+f"(d[3])
        : "r"(a[0]), "r"(a[1]), "r"(a[2]), "r"(a[3]), "r"(b[0]), "r"(b[1]));
}

// ---------------- smem layout ----------------
#define CHUNK_K   32
#define NCHUNK    8
#define ROWF      36                       // floats/row incl. pad 4
#define TILEF     (128 * ROWF)             // 4608 floats
#define TILE_BYTES (TILEF * 4)             // 18432
#define OFF_TILES 0                        // 4 tiles: buf0{A,B}, buf1{A,B}
#define OFF_ROWS  (4 * TILE_BYTES)         // 73728, 128 int
#define OFF_EN    (OFF_ROWS + 512)         // 128 float
#define OFF_SEL   (OFF_EN + 512)           // 128 int
#define OFF_NC    (OFF_SEL + 512)          // 128 int
#define OFF_CAND  (OFF_NC + 512)           // 128*8 int
#define OFF_LOSS  (OFF_CAND + 4096)        // 256 float
#define OFF_PMIN  (OFF_LOSS + 1024)        // 256 float
#define OFF_PCOL  (OFF_PMIN + 1024)        // 256 int
#define OFF_RMIN  (OFF_PCOL + 1024)        // 128 float
#define SMEM_DYN  (OFF_RMIN + 512)

// ---------------- main kernel ----------------
__global__ void __launch_bounds__(256, 2) vq_mma_kernel(
    const float* __restrict__ z, const float* __restrict__ cb,
    float* __restrict__ out)
{
    extern __shared__ char sm[];
    const int g   = blockIdx.y;
    const int tid = threadIdx.x;
    const int cnt   = g_counts[g];
    const int start = blockIdx.x * TM;
    if (start >= cnt) return;

    int*   s_rows = (int*)  (sm + OFF_ROWS);
    float* s_en   = (float*)(sm + OFF_EN);
    int*   s_sel  = (int*)  (sm + OFF_SEL);
    int*   s_nc   = (int*)  (sm + OFF_NC);
    int*   s_cand = (int*)  (sm + OFF_CAND);
    float* s_loss = (float*)(sm + OFF_LOSS);
    float* s_pmin = (float*)(sm + OFF_PMIN);
    int*   s_pcol = (int*)  (sm + OFF_PCOL);
    float* s_rmin = (float*)(sm + OFF_RMIN);

    if (tid < TM) {
        int r = (start + tid < cnt) ? g_buckets[g * B_ROWS + start + tid] : -1;
        s_rows[tid] = r;
        s_nc[tid] = 0;
        s_en[tid] = g_enorm[g * QSIZE + tid];
    }
    __syncthreads();

    // ---- async loader setup: 4 16B segments per tile per thread ----
    const unsigned sb = smem_u32(sm);
    const float* zsrc[4];
    const float* esrc[4];
    unsigned sdst[4];
    #pragma unroll
    for (int k = 0; k < 4; ++k) {
        int idx = tid + 256 * k;
        int row = idx >> 3, cs = idx & 7;
        int r = s_rows[row];
        zsrc[k] = z  + (size_t)(r < 0 ? 0 : r) * D_EMB + cs * 4;
        esrc[k] = cb + (size_t)(g * QSIZE + row) * D_EMB + cs * 4;
        sdst[k] = (unsigned)(row * ROWF + cs * 4) * 4;
    }

    // 2-D warp tiling (as R7): 4x2 warps, warp tile 32 rows x 64 cols
    const int w = tid >> 5, lane = tid & 31;
    const int gq = lane >> 2, t = lane & 3;
    const int wm = w >> 1, wn = w & 1;
    const int RW = wm * 32, CW = wn * 64;

    float acc[2][8][4];
    #pragma unroll
    for (int i = 0; i < 2; ++i)
        #pragma unroll
        for (int nf = 0; nf < 8; ++nf)
            #pragma unroll
            for (int q = 0; q < 4; ++q) acc[i][nf][q] = 0.f;

    // issue chunks 0 and 1
    #pragma unroll
    for (int c0 = 0; c0 < 2; ++c0) {
        unsigned abuf = sb + (c0 & 1) * 2 * TILE_BYTES;
        #pragma unroll
        for (int k = 0; k < 4; ++k) cp16(abuf + sdst[k], zsrc[k] + c0 * CHUNK_K);
        #pragma unroll
        for (int k = 0; k < 4; ++k)
            cp16(abuf + TILE_BYTES + sdst[k], esrc[k] + c0 * CHUNK_K);
        CP_COMMIT();
    }

    #pragma unroll 1
    for (int c = 0; c < NCHUNK; ++c) {
        if (c == NCHUNK - 1) { CP_WAIT0(); } else { CP_WAIT1(); }
        __syncthreads();

        const float* smA = (const float*)(sm + (c & 1) * 2 * TILE_BYTES);
        const float* smB = smA + TILEF;

        #pragma unroll
        for (int ks = 0; ks < 4; ++ks) {
            unsigned a[2][4];
            #pragma unroll
            for (int i = 0; i < 2; ++i) {
                const unsigned abase =
                    (unsigned)(RW + i * 16 + gq) * ROWF + ks * 8 + t;
                a[i][0] = *(const unsigned*)(smA + abase);
                a[i][1] = *(const unsigned*)(smA + abase + 8 * ROWF);
                a[i][2] = *(const unsigned*)(smA + abase + 4);
                a[i][3] = *(const unsigned*)(smA + abase + 8 * ROWF + 4);
            }
            unsigned b[8][2];
            #pragma unroll
            for (int nf = 0; nf < 8; ++nf) {
                const unsigned bbase =
                    (unsigned)(CW + nf * 8 + gq) * ROWF + ks * 8 + t;
                b[nf][0] = *(const unsigned*)(smB + bbase);
                b[nf][1] = *(const unsigned*)(smB + bbase + 4);
            }
            #pragma unroll
            for (int i = 0; i < 2; ++i)
                #pragma unroll
                for (int nf = 0; nf < 8; ++nf)
                    mma_tf32(acc[i][nf], a[i], b[nf]);
        }
        __syncthreads();   // all reads of this buffer done

        if (c < NCHUNK - 2) {
            const int cn = c + 2;
            unsigned abuf = sb + (cn & 1) * 2 * TILE_BYTES;
            #pragma unroll
            for (int k = 0; k < 4; ++k)
                cp16(abuf + sdst[k], zsrc[k] + cn * CHUNK_K);
            #pragma unroll
            for (int k = 0; k < 4; ++k)
                cp16(abuf + TILE_BYTES + sdst[k], esrc[k] + cn * CHUNK_K);
            CP_COMMIT();
        }
    }

    // ---- per-warp partial argmin (score = en - 2*dot; zn is constant/row) --
    #pragma unroll
    for (int i = 0; i < 2; ++i) {
        #pragma unroll
        for (int h = 0; h < 2; ++h) {
            const int row = RW + i * 16 + gq + h * 8;
            float v = CUDART_INF_F;  int cbest = 0x7fffffff;
            #pragma unroll
            for (int nf = 0; nf < 8; ++nf) {
                #pragma unroll
                for (int q = 0; q < 2; ++q) {
                    int col = CW + nf * 8 + 2 * t + q;
                    float s = fmaf(-2.f, acc[i][nf][h * 2 + q], s_en[col]);
                    if (s < v || (s == v && col < cbest)) { v = s; cbest = col; }
                }
            }
            #pragma unroll
            for (int off = 1; off < 4; off <<= 1) {
                float v2 = __shfl_xor_sync(0xffffffffu, v, off);
                int   c2 = __shfl_xor_sync(0xffffffffu, cbest, off);
                if (v2 < v || (v2 == v && c2 < cbest)) { v = v2; cbest = c2; }
            }
            if (t == 0) {
                s_pmin[row * 2 + wn] = v;
                s_pcol[row * 2 + wn] = cbest;
            }
        }
    }
    __syncthreads();

    if (tid < TM) {
        float v0 = s_pmin[tid * 2], v1 = s_pmin[tid * 2 + 1];
        int   c0 = s_pcol[tid * 2], c1 = s_pcol[tid * 2 + 1];
        bool take1 = (v1 < v0) || (v1 == v0 && c1 < c0);
        s_rmin[tid] = take1 ? v1 : v0;
        s_sel[tid]  = take1 ? c1 : c0;
    }
    __syncthreads();

    // ---- candidate collection within MARGIN of row min ----
    #pragma unroll
    for (int i = 0; i < 2; ++i) {
        #pragma unroll
        for (int h = 0; h < 2; ++h) {
            const int row = RW + i * 16 + gq + h * 8;
            const float thr = s_rmin[row] + MARGIN;
            #pragma unroll
            for (int nf = 0; nf < 8; ++nf) {
                #pragma unroll
                for (int q = 0; q < 2; ++q) {
                    int col = CW + nf * 8 + 2 * t + q;
                    float s = fmaf(-2.f, acc[i][nf][h * 2 + q], s_en[col]);
                    if (s <= thr) {
                        int p = atomicAdd(&s_nc[row], 1);
                        if (p < 8) s_cand[row * 8 + p] = col;
                    }
                }
            }
        }
    }
    __syncthreads();

    // ---- exact fp32 rescue for ambiguous rows (warp per 16-row slice) ----
    for (int m = w * 16; m < w * 16 + 16; ++m) {
        int nc = s_nc[m];
        int r  = s_rows[m];
        if (r < 0 || nc <= 1) continue;
        const float* zr = z + (size_t)r * D_EMB;
        float zn = 0.f;
        #pragma unroll
        for (int j = 0; j < 8; ++j)
            zn = fmaf(zr[lane + 32 * j], zr[lane + 32 * j], zn);
        #pragma unroll
        for (int off = 16; off; off >>= 1)
            zn += __shfl_xor_sync(0xffffffffu, zn, off);
        float bestv = CUDART_INF_F;  int bestc = 0x7fffffff;
        int nit = (nc <= 8) ? nc : QSIZE;
        for (int i = 0; i < nit; ++i) {
            int col = (nc <= 8) ? s_cand[m * 8 + i] : i;
            const float* er = cb + (size_t)(g * QSIZE + col) * D_EMB;
            float p = 0.f;
            #pragma unroll
            for (int j = 0; j < 8; ++j)
                p = fmaf(zr[lane + 32 * j], er[lane + 32 * j], p);
            #pragma unroll
            for (int off = 16; off; off >>= 1)
                p += __shfl_xor_sync(0xffffffffu, p, off);
            float sc = fmaf(-2.f, p, zn + s_en[col]);
            if (sc < bestv || (sc == bestv && col < bestc)) { bestv = sc; bestc = col; }
        }
        if (lane == 0) s_sel[m] = bestc;
    }
    __syncthreads();

    if (tid < TM) {
        int r = s_rows[tid];
        if (r >= 0) out[2 + r] = (float)(g * QSIZE + s_sel[tid]);
    }

    // ---- epilogue: st = z + (q - z), per-row loss ----
    {
        int m = tid >> 1, h = tid & 1;
        int r = s_rows[m];
        float lsum = 0.f;
        if (r >= 0) {
            int code = g * QSIZE + s_sel[m];
            const float* zr = z  + (size_t)r    * D_EMB + h * 128;
            const float* qr = cb + (size_t)code * D_EMB + h * 128;
            float* so = out + 2 + B_ROWS + (size_t)r * D_EMB + h * 128;
            #pragma unroll 4
            for (int cc = 0; cc < 128; cc += 4) {
                float4 zv = *(const float4*)(zr + cc);
                float4 qv = *(const float4*)(qr + cc);
                float dx = qv.x - zv.x, dy = qv.y - zv.y;
                float dz = qv.z - zv.z, dw = qv.w - zv.w;
                *(float2*)(so + cc)     = make_float2(zv.x + dx, zv.y + dy);
                *(float2*)(so + cc + 2) = make_float2(zv.z + dz, zv.w + dw);
                lsum += dx * dx; lsum += dy * dy; lsum += dz * dz; lsum += dw * dw;
            }
        }
        s_loss[tid] = lsum;
    }
    __syncthreads();
    if (tid < TM) {
        int r = s_rows[tid];
        if (r >= 0) g_rowloss[r] = s_loss[2 * tid] + s_loss[2 * tid + 1];
    }
}

// ---------------- loss reduction ----------------
__global__ void rowloss_reduce_kernel() {
    __shared__ double sd[256];
    int base = blockIdx.x * 512;
    double s = (double)g_rowloss[base + threadIdx.x]
             + (double)g_rowloss[base + 256 + threadIdx.x];
    sd[threadIdx.x] = s;
    __syncthreads();
    #pragma unroll
    for (int o = 128; o; o >>= 1) {
        if (threadIdx.x < o) sd[threadIdx.x] += sd[threadIdx.x + o];
        __syncthreads();
    }
    if (threadIdx.x == 0) g_bsum[blockIdx.x] = sd[0];
}

__global__ void finalize_kernel(float* __restrict__ out) {
    __shared__ double sd[256];
    sd[threadIdx.x] = g_bsum[threadIdx.x];
    __syncthreads();
    #pragma unroll
    for (int o = 128; o; o >>= 1) {
        if (threadIdx.x < o) sd[threadIdx.x] += sd[threadIdx.x + o];
        __syncthreads();
    }
    if (threadIdx.x == 0) {
        float vq = (float)(sd[0] / ((double)B_ROWS * (double)D_EMB));
        out[0] = vq;
        out[1] = 0.25f * vq;
    }
}

// ---------------- launch ----------------
extern "C" void kernel_launch(void* const* d_in, const int* in_sizes, int n_in,
                              void* d_out, int out_size) {
    const int*   node_type = (const int*)d_in[0];
    const float* z         = (const float*)d_in[1];
    const float* cb        = (const float*)d_in[2];
    float* out = (float*)d_out;

    cudaFuncSetAttribute(vq_mma_kernel,
                         cudaFuncAttributeMaxDynamicSharedMemorySize, SMEM_DYN);

    reset_kernel<<<1, 32>>>();
    classify_kernel<<<B_ROWS / 256, 256>>>(node_type);
    enorm_kernel<<<64, 256>>>(cb);
    dim3 grid(TILES_M, 4);
    vq_mma_kernel<<<grid, 256, SMEM_DYN>>>(z, cb, out);   // launch #4 -> ncu slot
    rowloss_reduce_kernel<<<256, 256>>>();
    finalize_kernel<<<1, 256>>>(out);
}

// round 9
// speedup vs baseline: 2.0656x; 1.9932x over previous
#include <cuda_runtime.h>
#include <math_constants.h>

#define B_ROWS   131072
#define D_EMB    256
#define QSIZE    128
#define TM       64
#define TILES_M  (B_ROWS / TM)   // 2048
#define MARGIN   1.5f

// ---------------- device scratch (static) ----------------
__device__ int    g_counts[4];
__device__ int    g_buckets[4 * B_ROWS];
__device__ float  g_enorm[512];
__device__ float  g_rowloss[B_ROWS];
__device__ double g_bsum[256];

// ---------------- small kernels ----------------
__global__ void reset_kernel() {
    if (threadIdx.x < 4) g_counts[threadIdx.x] = 0;
}
__global__ void classify_kernel(const int* __restrict__ node_type) {
    __shared__ int s_cnt[4];
    __shared__ int s_base[4];
    int tid = threadIdx.x;
    int i = blockIdx.x * blockDim.x + tid;
    if (tid < 4) s_cnt[tid] = 0;
    __syncthreads();
    int t = node_type[i];
    int g = (t == 5) ? 0 : (t == 6) ? 1 : (t == 7) ? 2 : 3;
    int p = atomicAdd(&s_cnt[g], 1);
    __syncthreads();
    if (tid < 4) s_base[tid] = atomicAdd(&g_counts[tid], s_cnt[tid]);
    __syncthreads();
    g_buckets[g * B_ROWS + s_base[g] + p] = i;
}
__global__ void enorm_kernel(const float* __restrict__ cb) {
    int code = blockIdx.x * 8 + (threadIdx.x >> 5);
    int lane = threadIdx.x & 31;
    const float* row = cb + (size_t)code * D_EMB;
    float s = 0.f;
    #pragma unroll
    for (int j = 0; j < 8; ++j)
        s = fmaf(row[lane + 32 * j], row[lane + 32 * j], s);
    #pragma unroll
    for (int o = 16; o; o >>= 1) s += __shfl_xor_sync(0xffffffffu, s, o);
    if (lane == 0) g_enorm[code] = s;
}

// ---------------- cp.async helpers ----------------
__device__ __forceinline__ unsigned smem_u32(const void* p) {
    unsigned a;
    asm("{ .reg .u64 t; cvta.to.shared.u64 t, %1; cvt.u32.u64 %0, t; }"
        : "=r"(a) : "l"(p));
    return a;
}
__device__ __forceinline__ void cp16(unsigned saddr, const void* gaddr) {
    asm volatile("cp.async.cg.shared.global [%0], [%1], 16;"
                 :: "r"(saddr), "l"(gaddr) : "memory");
}
#define CP_COMMIT() asm volatile("cp.async.commit_group;" ::: "memory")
#define CP_WAIT1()  asm volatile("cp.async.wait_group 1;" ::: "memory")
#define CP_WAIT0()  asm volatile("cp.async.wait_group 0;" ::: "memory")

__device__ __forceinline__ void mma_tf32(float* d, const unsigned* a,
                                         const unsigned* b) {
    asm volatile(
        "mma.sync.aligned.m16n8k8.row.col.f32.tf32.tf32.f32 "
        "{%0,%1,%2,%3}, {%4,%5,%6,%7}, {%8,%9}, {%0,%1,%2,%3};"
        : "+f"(d[0]), "+f"(d[1]), "+f"(d[2]), "+f"(d[3])
        : "r"(a[0]), "r"(a[1]), "r"(a[2]), "r"(a[3]), "r"(b[0]), "r"(b[1]));
}

// ---------------- smem layout ----------------
#define CHUNK_K   32
#define NCHUNK    8
#define ROWF      36
#define TA_BYTES  (TM * ROWF * 4)          // 9216
#define TB_BYTES  (128 * ROWF * 4)         // 18432
#define BUF_BYTES (TA_BYTES + TB_BYTES)    // 27648
#define OFF_ROWS  (2 * BUF_BYTES)          // 55296, 64 int
#define OFF_EN    (OFF_ROWS + 256)         // 128 float
#define OFF_SEL   (OFF_EN + 512)           // 64 int
#define OFF_NC    (OFF_SEL + 256)          // 64 int
#define OFF_CAND  (OFF_NC + 256)           // 64*8 int
#define OFF_PMIN  (OFF_CAND + 2048)        // 128 float
#define OFF_PCOL  (OFF_PMIN + 512)         // 128 int
#define OFF_RMIN  (OFF_PCOL + 512)         // 64 float
#define SMEM_DYN  (OFF_RMIN + 256)         // ~59.9 KB -> 3 CTAs/SM

// ---------------- main kernel ----------------
__global__ void __launch_bounds__(256, 3) vq_mma_kernel(
    const float* __restrict__ z, const float* __restrict__ cb,
    float* __restrict__ out)
{
    extern __shared__ char sm[];
    const int g   = blockIdx.y;
    const int tid = threadIdx.x;
    const int cnt   = g_counts[g];
    const int start = blockIdx.x * TM;
    if (start >= cnt) return;

    int*   s_rows = (int*)  (sm + OFF_ROWS);
    float* s_en   = (float*)(sm + OFF_EN);
    int*   s_sel  = (int*)  (sm + OFF_SEL);
    int*   s_nc   = (int*)  (sm + OFF_NC);
    int*   s_cand = (int*)  (sm + OFF_CAND);
    float* s_pmin = (float*)(sm + OFF_PMIN);
    int*   s_pcol = (int*)  (sm + OFF_PCOL);
    float* s_rmin = (float*)(sm + OFF_RMIN);

    if (tid < TM) {
        int r = (start + tid < cnt) ? g_buckets[g * B_ROWS + start + tid] : -1;
        s_rows[tid] = r;
        s_nc[tid] = 0;
    }
    if (tid >= 128 && tid < 256) s_en[tid - 128] = g_enorm[g * QSIZE + tid - 128];
    __syncthreads();

    // ---- async loader: A = 2 segs/thread, B = 4 segs/thread ----
    const unsigned sb = smem_u32(sm);
    const float* zsrc[2];  unsigned adst[2];
    const float* esrc[4];  unsigned bdst[4];
    #pragma unroll
    for (int k = 0; k < 2; ++k) {
        int idx = tid + 256 * k;
        int row = idx >> 3, cs = idx & 7;
        int r = s_rows[row];
        zsrc[k] = z + (size_t)(r < 0 ? 0 : r) * D_EMB + cs * 4;
        adst[k] = (unsigned)(row * ROWF + cs * 4) * 4;
    }
    #pragma unroll
    for (int k = 0; k < 4; ++k) {
        int idx = tid + 256 * k;
        int row = idx >> 3, cs = idx & 7;
        esrc[k] = cb + (size_t)(g * QSIZE + row) * D_EMB + cs * 4;
        bdst[k] = (unsigned)(TA_BYTES) + (unsigned)(row * ROWF + cs * 4) * 4;
    }

    // warp tiling: 4 warp-rows x 2 warp-cols; warp tile = 16 rows x 64 cols
    const int w = tid >> 5, lane = tid & 31;
    const int gq = lane >> 2, t = lane & 3;
    const int wm = w >> 1, wn = w & 1;
    const int R0 = wm * 16, CW = wn * 64;

    float acc[8][4];
    #pragma unroll
    for (int nf = 0; nf < 8; ++nf)
        #pragma unroll
        for (int q = 0; q < 4; ++q) acc[nf][q] = 0.f;

    #pragma unroll
    for (int c0 = 0; c0 < 2; ++c0) {
        unsigned buf = sb + (c0 & 1) * BUF_BYTES;
        #pragma unroll
        for (int k = 0; k < 2; ++k) cp16(buf + adst[k], zsrc[k] + c0 * CHUNK_K);
        #pragma unroll
        for (int k = 0; k < 4; ++k) cp16(buf + bdst[k], esrc[k] + c0 * CHUNK_K);
        CP_COMMIT();
    }

    #pragma unroll 1
    for (int c = 0; c < NCHUNK; ++c) {
        if (c == NCHUNK - 1) { CP_WAIT0(); } else { CP_WAIT1(); }
        __syncthreads();

        const float* smA = (const float*)(sm + (c & 1) * BUF_BYTES);
        const float* smB = smA + TM * ROWF;

        #pragma unroll
        for (int ks = 0; ks < 4; ++ks) {
            unsigned a[4];
            const unsigned abase = (unsigned)(R0 + gq) * ROWF + ks * 8 + t;
            a[0] = *(const unsigned*)(smA + abase);
            a[1] = *(const unsigned*)(smA + abase + 8 * ROWF);
            a[2] = *(const unsigned*)(smA + abase + 4);
            a[3] = *(const unsigned*)(smA + abase + 8 * ROWF + 4);
            unsigned b[8][2];
            #pragma unroll
            for (int nf = 0; nf < 8; ++nf) {
                const unsigned bbase =
                    (unsigned)(CW + nf * 8 + gq) * ROWF + ks * 8 + t;
                b[nf][0] = *(const unsigned*)(smB + bbase);
                b[nf][1] = *(const unsigned*)(smB + bbase + 4);
            }
            #pragma unroll
            for (int nf = 0; nf < 8; ++nf)
                mma_tf32(acc[nf], a, b[nf]);
        }
        __syncthreads();

        if (c < NCHUNK - 2) {
            const int cn = c + 2;
            unsigned buf = sb + (cn & 1) * BUF_BYTES;
            #pragma unroll
            for (int k = 0; k < 2; ++k) cp16(buf + adst[k], zsrc[k] + cn * CHUNK_K);
            #pragma unroll
            for (int k = 0; k < 4; ++k) cp16(buf + bdst[k], esrc[k] + cn * CHUNK_K);
            CP_COMMIT();
        }
    }

    // ---- per-warp partial argmin (score = en - 2*dot) ----
    #pragma unroll
    for (int h = 0; h < 2; ++h) {
        const int row = R0 + gq + h * 8;
        float v = CUDART_INF_F;  int cbest = 0x7fffffff;
        #pragma unroll
        for (int nf = 0; nf < 8; ++nf) {
            #pragma unroll
            for (int q = 0; q < 2; ++q) {
                int col = CW + nf * 8 + 2 * t + q;
                float s = fmaf(-2.f, acc[nf][h * 2 + q], s_en[col]);
                if (s < v || (s == v && col < cbest)) { v = s; cbest = col; }
            }
        }
        #pragma unroll
        for (int off = 1; off < 4; off <<= 1) {
            float v2 = __shfl_xor_sync(0xffffffffu, v, off);
            int   c2 = __shfl_xor_sync(0xffffffffu, cbest, off);
            if (v2 < v || (v2 == v && c2 < cbest)) { v = v2; cbest = c2; }
        }
        if (t == 0) {
            s_pmin[row * 2 + wn] = v;
            s_pcol[row * 2 + wn] = cbest;
        }
    }
    __syncthreads();

    if (tid < TM) {
        float v0 = s_pmin[tid * 2], v1 = s_pmin[tid * 2 + 1];
        int   c0 = s_pcol[tid * 2], c1 = s_pcol[tid * 2 + 1];
        bool take1 = (v1 < v0) || (v1 == v0 && c1 < c0);
        s_rmin[tid] = take1 ? v1 : v0;
        s_sel[tid]  = take1 ? c1 : c0;
    }
    __syncthreads();

    // ---- candidate collection within MARGIN of row min ----
    #pragma unroll
    for (int h = 0; h < 2; ++h) {
        const int row = R0 + gq + h * 8;
        const float thr = s_rmin[row] + MARGIN;
        #pragma unroll
        for (int nf = 0; nf < 8; ++nf) {
            #pragma unroll
            for (int q = 0; q < 2; ++q) {
                int col = CW + nf * 8 + 2 * t + q;
                float s = fmaf(-2.f, acc[nf][h * 2 + q], s_en[col]);
                if (s <= thr) {
                    int p = atomicAdd(&s_nc[row], 1);
                    if (p < 8) s_cand[row * 8 + p] = col;
                }
            }
        }
    }
    __syncthreads();

    // ---- exact fp32 rescue for ambiguous rows (warp per 8-row slice) ----
    for (int m = w * 8; m < w * 8 + 8; ++m) {
        int nc = s_nc[m];
        int r  = s_rows[m];
        if (r < 0 || nc <= 1) continue;
        const float* zr = z + (size_t)r * D_EMB;
        float zn = 0.f;
        #pragma unroll
        for (int j = 0; j < 8; ++j)
            zn = fmaf(zr[lane + 32 * j], zr[lane + 32 * j], zn);
        #pragma unroll
        for (int off = 16; off; off >>= 1)
            zn += __shfl_xor_sync(0xffffffffu, zn, off);
        float bestv = CUDART_INF_F;  int bestc = 0x7fffffff;
        int nit = (nc <= 8) ? nc : QSIZE;
        for (int i = 0; i < nit; ++i) {
            int col = (nc <= 8) ? s_cand[m * 8 + i] : i;
            const float* er = cb + (size_t)(g * QSIZE + col) * D_EMB;
            float p = 0.f;
            #pragma unroll
            for (int j = 0; j < 8; ++j)
                p = fmaf(zr[lane + 32 * j], er[lane + 32 * j], p);
            #pragma unroll
            for (int off = 16; off; off >>= 1)
                p += __shfl_xor_sync(0xffffffffu, p, off);
            float sc = fmaf(-2.f, p, zn + s_en[col]);
            if (sc < bestv || (sc == bestv && col < bestc)) { bestv = sc; bestc = col; }
        }
        if (lane == 0) s_sel[m] = bestc;
    }
    __syncthreads();

    if (tid < TM) {
        int r = s_rows[tid];
        if (r >= 0) out[2 + r] = (float)(g * QSIZE + s_sel[tid]);
    }
}

// ---------------- epilogue: st = z + (q - z), per-row loss ----------------
// one warp per row; 8 rows per block
__global__ void __launch_bounds__(256) epilogue_kernel(
    const float* __restrict__ z, const float* __restrict__ cb,
    float* __restrict__ out)
{
    const int w = threadIdx.x >> 5, lane = threadIdx.x & 31;
    const int r = blockIdx.x * 8 + w;
    const int code = (int)out[2 + r];
    const float* zr = z  + (size_t)r * D_EMB;
    const float* qr = cb + (size_t)code * D_EMB;
    float* so = out + 2 + B_ROWS + (size_t)r * D_EMB;
    float lsum = 0.f;
    #pragma unroll
    for (int j = 0; j < 2; ++j) {
        int cc = lane * 4 + j * 128;
        float4 zv = *(const float4*)(zr + cc);
        float4 qv = *(const float4*)(qr + cc);
        float dx = qv.x - zv.x, dy = qv.y - zv.y;
        float dz = qv.z - zv.z, dw = qv.w - zv.w;
        *(float2*)(so + cc)     = make_float2(zv.x + dx, zv.y + dy);
        *(float2*)(so + cc + 2) = make_float2(zv.z + dz, zv.w + dw);
        lsum += dx * dx; lsum += dy * dy; lsum += dz * dz; lsum += dw * dw;
    }
    #pragma unroll
    for (int off = 16; off; off >>= 1)
        lsum += __shfl_xor_sync(0xffffffffu, lsum, off);
    if (lane == 0) g_rowloss[r] = lsum;
}

// ---------------- loss reduction ----------------
__global__ void rowloss_reduce_kernel() {
    __shared__ double sd[256];
    int base = blockIdx.x * 512;
    double s = (double)g_rowloss[base + threadIdx.x]
             + (double)g_rowloss[base + 256 + threadIdx.x];
    sd[threadIdx.x] = s;
    __syncthreads();
    #pragma unroll
    for (int o = 128; o; o >>= 1) {
        if (threadIdx.x < o) sd[threadIdx.x] += sd[threadIdx.x + o];
        __syncthreads();
    }
    if (threadIdx.x == 0) g_bsum[blockIdx.x] = sd[0];
}

__global__ void finalize_kernel(float* __restrict__ out) {
    __shared__ double sd[256];
    sd[threadIdx.x] = g_bsum[threadIdx.x];
    __syncthreads();
    #pragma unroll
    for (int o = 128; o; o >>= 1) {
        if (threadIdx.x < o) sd[threadIdx.x] += sd[threadIdx.x + o];
        __syncthreads();
    }
    if (threadIdx.x == 0) {
        float vq = (float)(sd[0] / ((double)B_ROWS * (double)D_EMB));
        out[0] = vq;
        out[1] = 0.25f * vq;
    }
}

// ---------------- launch ----------------
extern "C" void kernel_launch(void* const* d_in, const int* in_sizes, int n_in,
                              void* d_out, int out_size) {
    const int*   node_type = (const int*)d_in[0];
    const float* z         = (const float*)d_in[1];
    const float* cb        = (const float*)d_in[2];
    float* out = (float*)d_out;

    cudaFuncSetAttribute(vq_mma_kernel,
                         cudaFuncAttributeMaxDynamicSharedMemorySize, SMEM_DYN);

    reset_kernel<<<1, 32>>>();
    classify_kernel<<<B_ROWS / 256, 256>>>(node_type);
    enorm_kernel<<<64, 256>>>(cb);
    dim3 grid(TILES_M, 4);
    vq_mma_kernel<<<grid, 256, SMEM_DYN>>>(z, cb, out);
    epilogue_kernel<<<B_ROWS / 8, 256>>>(z, cb, out);
    rowloss_reduce_kernel<<<256, 256>>>();
    finalize_kernel<<<1, 256>>>(out);
}